// round 6
// baseline (speedup 1.0000x reference)
#include <cuda_runtime.h>
#include <math.h>

// ContrastiveLoss, B=4096, D=1024, MARGIN=1.0, EPS=1e-8.
//
// MARGIN == 1.0 makes the off-diagonal hinge relu(cos_ij - 1) identically 0
// for unit vectors, so the loss reduces exactly to the diagonal terms. We read
// only the labels diagonal and stream the 3 feature matrices (48 MB).
//
// R6: R1(occ 43%) == R5(occ 87%) bit-identical at 10.75us -> streaming is NOT
// occ/MLP limited. Invariant across all runs: 512B-granularity interleave of 3
// streams ~16MB apart (DRAM page thrash). Now each warp issues per-stream
// CONTIGUOUS 2KB bursts (4x LDG.128 from one stream before switching) via
// __ldcv (L1 bypass - the path B300's measured BW cap used). Shape kept from
// R5: 2 warps/row, 1024 blocks x 256thr; regs float (~68).

#ifndef WARP_FULL_MASK
#define WARP_FULL_MASK 0xFFFFFFFFu
#endif

#define THREADS 256
#define NWARPS  (THREADS / 32)     // 8 warps -> 4 rows per block
#define ROWS_PER_BLOCK (NWARPS / 2)

static __device__ float g_partial[8192];   // per-row losses (B <= 8192)

__device__ __forceinline__ float warp_sum(float v) {
#pragma unroll
    for (int o = 16; o > 0; o >>= 1)
        v += __shfl_down_sync(WARP_FULL_MASK, v, o);
    return v;
}

// 2 warps per row: warp (2k+h) streams half h of row blockIdx.x*4+k.
// Half-row = D4/2 = 128 float4 -> one 4-deep batch per stream per chunk.
__global__ void
row_loss_kernel(const float4* __restrict__ f0,
                const float4* __restrict__ f1,
                const float4* __restrict__ t,
                const float*  __restrict__ labels,
                int B, int D4)
{
    __shared__ float s_red[NWARPS][5];

    int tid  = threadIdx.x;
    int lane = tid & 31;
    int wid  = tid >> 5;
    int rloc = wid >> 1;           // 0..3 row within block
    int half = wid & 1;            // which half of the row
    int row  = blockIdx.x * ROWS_PER_BLOCK + rloc;

    float d0 = 0.f, d1 = 0.f, n0 = 0.f, n1 = 0.f, nt = 0.f;

    if (row < B) {
        int h4 = D4 >> 1;                                  // 128 for D=1024
        size_t base = (size_t)row * D4 + (size_t)half * h4;
        const float4* r0 = f0 + base;
        const float4* r1 = f1 + base;
        const float4* rt = t  + base;

        int nchunk = h4 >> 7;      // chunks of 128 float4 (4/lane); 1 for D=1024

        for (int u = 0; u < nchunk; u++) {
            int off = (u << 7) + lane;
            float4 a[4], b[4], c[4];
            // Per-stream contiguous 2KB bursts: all of f0, then f1, then t.
#pragma unroll
            for (int j = 0; j < 4; j++) a[j] = __ldcv(r0 + off + j * 32);
#pragma unroll
            for (int j = 0; j < 4; j++) b[j] = __ldcv(r1 + off + j * 32);
#pragma unroll
            for (int j = 0; j < 4; j++) c[j] = __ldcv(rt + off + j * 32);
#pragma unroll
            for (int j = 0; j < 4; j++) {
                d0 += a[j].x * c[j].x + a[j].y * c[j].y + a[j].z * c[j].z + a[j].w * c[j].w;
                d1 += b[j].x * c[j].x + b[j].y * c[j].y + b[j].z * c[j].z + b[j].w * c[j].w;
                n0 += a[j].x * a[j].x + a[j].y * a[j].y + a[j].z * a[j].z + a[j].w * a[j].w;
                n1 += b[j].x * b[j].x + b[j].y * b[j].y + b[j].z * b[j].z + b[j].w * b[j].w;
                nt += c[j].x * c[j].x + c[j].y * c[j].y + c[j].z * c[j].z + c[j].w * c[j].w;
            }
        }
        // Generic remainder (not hit for D=1024).
        for (int i = (nchunk << 7) + lane; i < h4; i += 32) {
            float4 a = __ldcv(r0 + i);
            float4 b = __ldcv(r1 + i);
            float4 c = __ldcv(rt + i);
            d0 += a.x * c.x + a.y * c.y + a.z * c.z + a.w * c.w;
            d1 += b.x * c.x + b.y * c.y + b.z * c.z + b.w * c.w;
            n0 += a.x * a.x + a.y * a.y + a.z * a.z + a.w * a.w;
            n1 += b.x * b.x + b.y * b.y + b.z * b.z + b.w * b.w;
            nt += c.x * c.x + c.y * c.y + c.z * c.z + c.w * c.w;
        }
    }

    d0 = warp_sum(d0);
    d1 = warp_sum(d1);
    n0 = warp_sum(n0);
    n1 = warp_sum(n1);
    nt = warp_sum(nt);

    if (lane == 0) {
        s_red[wid][0] = d0;
        s_red[wid][1] = d1;
        s_red[wid][2] = n0;
        s_red[wid][3] = n1;
        s_red[wid][4] = nt;
    }
    __syncthreads();

    // 4 threads finish 4 rows: combine the two half-row partials.
    if (tid < ROWS_PER_BLOCK) {
        int r = blockIdx.x * ROWS_PER_BLOCK + tid;
        if (r < B) {
            float v0 = s_red[2 * tid][0] + s_red[2 * tid + 1][0];
            float v1 = s_red[2 * tid][1] + s_red[2 * tid + 1][1];
            float v2 = s_red[2 * tid][2] + s_red[2 * tid + 1][2];
            float v3 = s_red[2 * tid][3] + s_red[2 * tid + 1][3];
            float v4 = s_red[2 * tid][4] + s_red[2 * tid + 1][4];

            const float EPS = 1e-8f;
            float inv_t = 1.0f / fmaxf(sqrtf(v4), EPS);
            float cos0  = v0 * (1.0f / fmaxf(sqrtf(v2), EPS)) * inv_t;
            float cos1  = v1 * (1.0f / fmaxf(sqrtf(v3), EPS)) * inv_t;
            float L     = labels[(size_t)r * B + r];   // diagonal label
            g_partial[r] =
                  L * (1.0f - cos0) + (1.0f - L) * fmaxf(cos0 - 1.0f, 0.0f)
                + L * (1.0f - cos1) + (1.0f - L) * fmaxf(cos1 - 1.0f, 0.0f);
        }
    }
}

// Deterministic single-block reduction of the B per-row partials.
__global__ void __launch_bounds__(THREADS)
final_reduce_kernel(float* __restrict__ out, int B)
{
    __shared__ float sdata[NWARPS];
    int tid = threadIdx.x;

    float s = 0.f;
    for (int i = tid; i < B; i += THREADS)
        s += g_partial[i];

    s = warp_sum(s);
    if ((tid & 31) == 0) sdata[tid >> 5] = s;
    __syncthreads();

    if (tid < 32) {
        float v = (tid < NWARPS) ? sdata[tid] : 0.f;
#pragma unroll
        for (int o = NWARPS / 2; o > 0; o >>= 1)
            v += __shfl_down_sync(WARP_FULL_MASK, v, o);
        if (tid == 0)
            out[0] = v / ((float)B * (float)B);
    }
}

extern "C" void kernel_launch(void* const* d_in, const int* in_sizes, int n_in,
                              void* d_out, int out_size)
{
    const float* f0     = (const float*)d_in[0];
    const float* f1     = (const float*)d_in[1];
    const float* t      = (const float*)d_in[2];
    const float* labels = (const float*)d_in[3];

    long long nl = in_sizes[3];
    int B = (int)(sqrt((double)nl) + 0.5);
    int D = in_sizes[0] / B;
    int D4 = D / 4;

    int blocks = (B + ROWS_PER_BLOCK - 1) / ROWS_PER_BLOCK;  // 1024 for B=4096

    row_loss_kernel<<<blocks, THREADS>>>(
        (const float4*)f0, (const float4*)f1, (const float4*)t,
        labels, B, D4);

    final_reduce_kernel<<<1, THREADS>>>((float*)d_out, B);
}